// round 1
// baseline (speedup 1.0000x reference)
#include <cuda_runtime.h>

#define Bn 8
#define Tn 1024
#define IND 512
#define NH 8
#define HD 64
#define OUTD 512
#define MAXPOS 512

// -------- scratch (allocations are forbidden; use device globals) --------
__device__ float g_q[(size_t)Bn*NH*Tn*HD];     // 16 MB
__device__ float g_k[(size_t)Bn*NH*Tn*HD];     // 16 MB
__device__ float g_v[(size_t)Bn*NH*Tn*HD];     // 16 MB
__device__ float g_att[(size_t)Bn*Tn*OUTD];    // 16 MB

// ============================================================
// Kernel 1: fused QKV projection.
// X[8192,512] @ [Wq | Wkv][512,1536] + bias -> q/k/v in [b,h,t,d]
// 64x64 tile per block, BK=16, 256 threads, 4x4 micro-tile.
// ============================================================
__global__ __launch_bounds__(256) void qkv_kernel(
    const float* __restrict__ x,
    const float* __restrict__ Wq,  const float* __restrict__ bq,
    const float* __restrict__ Wkv, const float* __restrict__ bkv)
{
    __shared__ float s_a[64][16];
    __shared__ float s_b[16][64];

    const int tid = threadIdx.x;
    const int tx = tid & 15, ty = tid >> 4;
    const int row0 = blockIdx.y * 64;
    const int col0 = blockIdx.x * 64;          // 0..1535

    const float* Wp; int ldw; int wc; const float* bias;
    if (col0 < 512) { Wp = Wq;  ldw = 512;  wc = col0;       bias = bq  + col0; }
    else            { Wp = Wkv; ldw = 1024; wc = col0 - 512; bias = bkv + (col0 - 512); }

    const int a_row = tid >> 2;            // 0..63
    const int a_k   = (tid & 3) << 2;      // 0,4,8,12
    const int b_k   = tid >> 4;            // 0..15
    const int b_c   = (tid & 15) << 2;     // 0..60

    float acc[4][4] = {};

    for (int k0 = 0; k0 < IND; k0 += 16) {
        float4 av = *(const float4*)(x + (size_t)(row0 + a_row) * IND + (k0 + a_k));
        float4 bv = *(const float4*)(Wp + (size_t)(k0 + b_k) * ldw + (wc + b_c));
        *(float4*)&s_a[a_row][a_k] = av;
        *(float4*)&s_b[b_k][b_c]   = bv;
        __syncthreads();

#pragma unroll
        for (int kk = 0; kk < 16; kk++) {
            float a0 = s_a[ty*4+0][kk];
            float a1 = s_a[ty*4+1][kk];
            float a2 = s_a[ty*4+2][kk];
            float a3 = s_a[ty*4+3][kk];
            float4 b4 = *(float4*)&s_b[kk][tx*4];
            acc[0][0] += a0*b4.x; acc[0][1] += a0*b4.y; acc[0][2] += a0*b4.z; acc[0][3] += a0*b4.w;
            acc[1][0] += a1*b4.x; acc[1][1] += a1*b4.y; acc[1][2] += a1*b4.z; acc[1][3] += a1*b4.w;
            acc[2][0] += a2*b4.x; acc[2][1] += a2*b4.y; acc[2][2] += a2*b4.z; acc[2][3] += a2*b4.w;
            acc[3][0] += a3*b4.x; acc[3][1] += a3*b4.y; acc[3][2] += a3*b4.z; acc[3][3] += a3*b4.w;
        }
        __syncthreads();
    }

    // route to q / k / v buffer with [b,h,t,d] layout
    const int seg  = col0 >> 9;            // 0=q, 1=k, 2=v
    const int cloc = col0 & 511;
    const int h    = cloc >> 6;
    float* dst = (seg == 0) ? g_q : (seg == 1) ? g_k : g_v;

#pragma unroll
    for (int i = 0; i < 4; i++) {
        int r  = row0 + ty*4 + i;
        int bb = r >> 10, tt = r & 1023;
        float* drow = dst + ((size_t)(bb*NH + h) * Tn + tt) * HD + tx*4;
#pragma unroll
        for (int j = 0; j < 4; j++)
            drow[j] = acc[i][j] + bias[tx*4 + j];
    }
}

// ============================================================
// Kernel 2: flash-style attention with relative position bias.
// score(n,m) = scale * sum_d q[n,d] * (k[m,d] + rel_emb[clip(n-m)+512, d])
// Block: 64 query rows x one (b,h). 256 threads (16x16), 4x4 micro.
// ============================================================
#define SQ 65
#define ATTN_SMEM ((3*64*SQ + 127*SQ) * (int)sizeof(float))   // 82,940 B

__global__ __launch_bounds__(256) void attn_kernel(const float* __restrict__ rel_emb)
{
    extern __shared__ float sm[];
    float* s_q   = sm;                    // 64 x SQ
    float* s_k   = sm + 64*SQ;            // 64 x SQ
    float* s_v   = sm + 2*64*SQ;          // 64 x SQ
    float* s_rel = sm + 3*64*SQ;          // 127 x SQ  (aliased as P after scores)
    float* s_p   = s_rel;

    const int tid = threadIdx.x;
    const int tx = tid & 15, ty = tid >> 4;
    const int n0 = blockIdx.x * 64;
    const int bh = blockIdx.y;
    const float scale = 0.125f;           // 1/sqrt(64)

    const size_t base = (size_t)bh * Tn * HD;

    // load Q tile once
    for (int e = tid; e < 64*64; e += 256) {
        int i = e >> 6, d = e & 63;
        s_q[i*SQ + d] = g_q[base + (size_t)(n0 + i)*HD + d];
    }

    float o[4][4] = {};
    float mi[4] = {-1e30f, -1e30f, -1e30f, -1e30f};
    float li[4] = {0.f, 0.f, 0.f, 0.f};

    // rel row for (i-j) == -3 at this thread's micro-tile: 4*(ty-tx)+63-3
    const int dbase = 4*(ty - tx) + 60;   // in [0,120]

    for (int m0 = 0; m0 < Tn; m0 += 64) {
        // load K, V tiles
        for (int e = tid; e < 64*64; e += 256) {
            int i = e >> 6, d = e & 63;
            s_k[i*SQ + d] = g_k[base + (size_t)(m0 + i)*HD + d];
            s_v[i*SQ + d] = g_v[base + (size_t)(m0 + i)*HD + d];
        }
        // load 127 relative-embedding rows for this (n-tile, m-tile)
        const int delta0 = n0 - m0;
        for (int e = tid; e < 127*64; e += 256) {
            int r = e >> 6, d = e & 63;
            int dd = delta0 + r - 63;
            dd = (dd < -MAXPOS) ? -MAXPOS : (dd > MAXPOS ? MAXPOS : dd);
            s_rel[r*SQ + d] = rel_emb[(size_t)(dd + MAXPOS)*HD + d];
        }
        __syncthreads();

        // ---- scores: S = Q (K + Rel)^T ----
        float s[4][4] = {};
#pragma unroll 4
        for (int d = 0; d < 64; d++) {
            float qv[4], kv[4], rv[7];
#pragma unroll
            for (int i = 0; i < 4; i++) qv[i] = s_q[(ty*4+i)*SQ + d];
#pragma unroll
            for (int j = 0; j < 4; j++) kv[j] = s_k[(tx*4+j)*SQ + d];
#pragma unroll
            for (int u = 0; u < 7; u++) rv[u] = s_rel[(dbase + u)*SQ + d];
#pragma unroll
            for (int i = 0; i < 4; i++)
#pragma unroll
                for (int j = 0; j < 4; j++)
                    s[i][j] += qv[i] * (kv[j] + rv[i - j + 3]);
        }
        __syncthreads();   // everyone done reading s_rel/s_k before P overwrite

#pragma unroll
        for (int i = 0; i < 4; i++)
#pragma unroll
            for (int j = 0; j < 4; j++)
                s[i][j] *= scale;

        // ---- online softmax (row groups = 16 lanes along tx) ----
#pragma unroll
        for (int i = 0; i < 4; i++) {
            float rmax = fmaxf(fmaxf(s[i][0], s[i][1]), fmaxf(s[i][2], s[i][3]));
#pragma unroll
            for (int off = 1; off < 16; off <<= 1)
                rmax = fmaxf(rmax, __shfl_xor_sync(0xffffffffu, rmax, off, 16));
            float nm   = fmaxf(mi[i], rmax);
            float corr = __expf(mi[i] - nm);
            float psum = 0.f;
#pragma unroll
            for (int j = 0; j < 4; j++) {
                float p = __expf(s[i][j] - nm);
                s[i][j] = p;
                psum += p;
            }
#pragma unroll
            for (int off = 1; off < 16; off <<= 1)
                psum += __shfl_xor_sync(0xffffffffu, psum, off, 16);
            li[i] = li[i] * corr + psum;
            mi[i] = nm;
#pragma unroll
            for (int j = 0; j < 4; j++) o[i][j] *= corr;
#pragma unroll
            for (int j = 0; j < 4; j++)
                s_p[(ty*4+i)*SQ + tx*4 + j] = s[i][j];
        }
        __syncthreads();

        // ---- O += P @ V ----
#pragma unroll 4
        for (int m = 0; m < 64; m++) {
            float pv[4], vv[4];
#pragma unroll
            for (int i = 0; i < 4; i++) pv[i] = s_p[(ty*4+i)*SQ + m];
#pragma unroll
            for (int j = 0; j < 4; j++) vv[j] = s_v[m*SQ + tx*4 + j];
#pragma unroll
            for (int i = 0; i < 4; i++)
#pragma unroll
                for (int j = 0; j < 4; j++)
                    o[i][j] += pv[i] * vv[j];
        }
        __syncthreads();   // before next tile's smem loads
    }

    // write normalized output to [b, t, h*64 + d]
    const int b_ = bh >> 3, h_ = bh & 7;
#pragma unroll
    for (int i = 0; i < 4; i++) {
        int t_ = n0 + ty*4 + i;
        float inv = 1.f / li[i];
        float4 w;
        w.x = o[i][0]*inv; w.y = o[i][1]*inv; w.z = o[i][2]*inv; w.w = o[i][3]*inv;
        *(float4*)(g_att + ((size_t)(b_*Tn + t_)*OUTD + h_*HD + tx*4)) = w;
    }
}

// ============================================================
// Kernel 3: output projection. g_att[8192,512] @ Wout + bout -> d_out
// ============================================================
__global__ __launch_bounds__(256) void out_kernel(
    const float* __restrict__ Wout, const float* __restrict__ bout,
    float* __restrict__ out)
{
    __shared__ float s_a[64][16];
    __shared__ float s_b[16][64];

    const int tid = threadIdx.x;
    const int tx = tid & 15, ty = tid >> 4;
    const int row0 = blockIdx.y * 64;
    const int col0 = blockIdx.x * 64;

    const int a_row = tid >> 2;
    const int a_k   = (tid & 3) << 2;
    const int b_k   = tid >> 4;
    const int b_c   = (tid & 15) << 2;

    float acc[4][4] = {};

    for (int k0 = 0; k0 < OUTD; k0 += 16) {
        float4 av = *(const float4*)(g_att + (size_t)(row0 + a_row) * OUTD + (k0 + a_k));
        float4 bv = *(const float4*)(Wout + (size_t)(k0 + b_k) * IND + (col0 + b_c));
        *(float4*)&s_a[a_row][a_k] = av;
        *(float4*)&s_b[b_k][b_c]   = bv;
        __syncthreads();

#pragma unroll
        for (int kk = 0; kk < 16; kk++) {
            float a0 = s_a[ty*4+0][kk];
            float a1 = s_a[ty*4+1][kk];
            float a2 = s_a[ty*4+2][kk];
            float a3 = s_a[ty*4+3][kk];
            float4 b4 = *(float4*)&s_b[kk][tx*4];
            acc[0][0] += a0*b4.x; acc[0][1] += a0*b4.y; acc[0][2] += a0*b4.z; acc[0][3] += a0*b4.w;
            acc[1][0] += a1*b4.x; acc[1][1] += a1*b4.y; acc[1][2] += a1*b4.z; acc[1][3] += a1*b4.w;
            acc[2][0] += a2*b4.x; acc[2][1] += a2*b4.y; acc[2][2] += a2*b4.z; acc[2][3] += a2*b4.w;
            acc[3][0] += a3*b4.x; acc[3][1] += a3*b4.y; acc[3][2] += a3*b4.z; acc[3][3] += a3*b4.w;
        }
        __syncthreads();
    }

#pragma unroll
    for (int i = 0; i < 4; i++) {
        int r = row0 + ty*4 + i;
        float* drow = out + (size_t)r * IND + col0 + tx*4;
#pragma unroll
        for (int j = 0; j < 4; j++)
            drow[j] = acc[i][j] + bout[col0 + tx*4 + j];
    }
}

// ============================================================
extern "C" void kernel_launch(void* const* d_in, const int* in_sizes, int n_in,
                              void* d_out, int out_size)
{
    const float* x    = (const float*)d_in[0];
    const float* Wq   = (const float*)d_in[1];
    const float* bq   = (const float*)d_in[2];
    const float* Wkv  = (const float*)d_in[3];
    const float* bkv  = (const float*)d_in[4];
    const float* Wout = (const float*)d_in[5];
    const float* bout = (const float*)d_in[6];
    const float* rel  = (const float*)d_in[7];
    float* out = (float*)d_out;

    cudaFuncSetAttribute(attn_kernel,
                         cudaFuncAttributeMaxDynamicSharedMemorySize, ATTN_SMEM);

    // QKV projection: 1536 cols / 64, 8192 rows / 64
    qkv_kernel<<<dim3(24, 128), 256>>>(x, Wq, bq, Wkv, bkv);

    // attention: 16 n-tiles x 64 (b,h) pairs
    attn_kernel<<<dim3(16, 64), 256, ATTN_SMEM>>>(rel);

    // output projection: 512 cols / 64, 8192 rows / 64
    out_kernel<<<dim3(8, 128), 256>>>(Wout, bout, out);
}

// round 2
// speedup vs baseline: 2.0557x; 2.0557x over previous
#include <cuda_runtime.h>

#define Bn 8
#define Tn 1024
#define IND 512
#define NH 8
#define HD 64
#define OUTD 512
#define MAXPOS 512

// -------- scratch (allocations forbidden; device globals) --------
__device__ float g_q[(size_t)Bn*NH*Tn*HD];
__device__ float g_k[(size_t)Bn*NH*Tn*HD];
__device__ float g_v[(size_t)Bn*NH*Tn*HD];
__device__ float g_att[(size_t)Bn*Tn*OUTD];

// -------- tf32 helpers --------
__device__ __forceinline__ unsigned f2tf(float f) {
    unsigned u; asm("cvt.rna.tf32.f32 %0, %1;" : "=r"(u) : "f"(f)); return u;
}
__device__ __forceinline__ float tfs(float f) { return __uint_as_float(f2tf(f)); }

__device__ __forceinline__ void mma8(float* c,
    unsigned a0, unsigned a1, unsigned a2, unsigned a3,
    unsigned b0, unsigned b1)
{
    asm volatile(
      "mma.sync.aligned.m16n8k8.row.col.f32.tf32.tf32.f32 "
      "{%0,%1,%2,%3},{%4,%5,%6,%7},{%8,%9},{%0,%1,%2,%3};"
      : "+f"(c[0]), "+f"(c[1]), "+f"(c[2]), "+f"(c[3])
      : "r"(a0), "r"(a1), "r"(a2), "r"(a3), "r"(b0), "r"(b1));
}

// ============================================================
// Kernel 1: QKV projection, tf32 mma. BM=128, BN=64, BK=16, 256 thr.
// ============================================================
__global__ __launch_bounds__(256) void qkv_mma(
    const float* __restrict__ x,
    const float* __restrict__ Wq,  const float* __restrict__ bq,
    const float* __restrict__ Wkv, const float* __restrict__ bkv)
{
    __shared__ float s_a[128*20];
    __shared__ float s_b[16*68];

    const int tid = threadIdx.x, lane = tid & 31, warp = tid >> 5;
    const int wr = warp >> 1, wc = warp & 1;          // 4x2 warp grid (32x32 each)
    const int lq = lane >> 2, lr = lane & 3;
    const int row0 = blockIdx.y * 128, col0 = blockIdx.x * 64;

    const float* W; int ldw; const float* bias;
    int wcol;
    if (col0 < OUTD) { W = Wq;  ldw = OUTD;   wcol = col0;        bias = bq  + col0; }
    else             { W = Wkv; ldw = 2*OUTD; wcol = col0 - OUTD; bias = bkv + (col0 - OUTD); }

    const int ar = tid >> 2, ak = (tid & 3) << 2;       // A: 2 float4/thread
    const int bk = tid >> 4, bn = (tid & 15) << 2;      // B: 1 float4/thread

    float acc[2][4][4];
#pragma unroll
    for (int i = 0; i < 2; i++)
#pragma unroll
        for (int j = 0; j < 4; j++)
#pragma unroll
            for (int e = 0; e < 4; e++) acc[i][j][e] = 0.f;

    for (int k0 = 0; k0 < IND; k0 += 16) {
        float4 a0v = *(const float4*)(x + (size_t)(row0 + ar)      * IND + k0 + ak);
        float4 a1v = *(const float4*)(x + (size_t)(row0 + ar + 64) * IND + k0 + ak);
        float4 bv  = *(const float4*)(W + (size_t)(k0 + bk) * ldw + wcol + bn);
        __syncthreads();
        s_a[ ar      *20 + ak+0] = tfs(a0v.x); s_a[ ar      *20 + ak+1] = tfs(a0v.y);
        s_a[ ar      *20 + ak+2] = tfs(a0v.z); s_a[ ar      *20 + ak+3] = tfs(a0v.w);
        s_a[(ar + 64)*20 + ak+0] = tfs(a1v.x); s_a[(ar + 64)*20 + ak+1] = tfs(a1v.y);
        s_a[(ar + 64)*20 + ak+2] = tfs(a1v.z); s_a[(ar + 64)*20 + ak+3] = tfs(a1v.w);
        s_b[bk*68 + bn+0] = tfs(bv.x); s_b[bk*68 + bn+1] = tfs(bv.y);
        s_b[bk*68 + bn+2] = tfs(bv.z); s_b[bk*68 + bn+3] = tfs(bv.w);
        __syncthreads();

#pragma unroll
        for (int ks = 0; ks < 2; ks++) {
            unsigned a[2][4], b[4][2];
#pragma unroll
            for (int rt = 0; rt < 2; rt++) {
                int r = wr*32 + rt*16 + lq, k = ks*8 + lr;
                a[rt][0] = __float_as_uint(s_a[ r   *20 + k]);
                a[rt][1] = __float_as_uint(s_a[(r+8)*20 + k]);
                a[rt][2] = __float_as_uint(s_a[ r   *20 + k+4]);
                a[rt][3] = __float_as_uint(s_a[(r+8)*20 + k+4]);
            }
#pragma unroll
            for (int ct = 0; ct < 4; ct++) {
                int n = wc*32 + ct*8 + lq, k = ks*8 + lr;
                b[ct][0] = __float_as_uint(s_b[ k   *68 + n]);
                b[ct][1] = __float_as_uint(s_b[(k+4)*68 + n]);
            }
#pragma unroll
            for (int rt = 0; rt < 2; rt++)
#pragma unroll
                for (int ct = 0; ct < 4; ct++)
                    mma8(acc[rt][ct], a[rt][0],a[rt][1],a[rt][2],a[rt][3], b[ct][0],b[ct][1]);
        }
    }

    // epilogue: route into q/k/v [b,h,t,d]
    const int seg = col0 >> 9;
    const int h   = (col0 & 511) >> 6;
    float* dst = (seg == 0) ? g_q : (seg == 1) ? g_k : g_v;

#pragma unroll
    for (int rt = 0; rt < 2; rt++)
#pragma unroll
        for (int ct = 0; ct < 4; ct++)
#pragma unroll
            for (int hh = 0; hh < 2; hh++) {
                int r  = row0 + wr*32 + rt*16 + lq + 8*hh;
                int bb = r >> 10, tt = r & 1023;
                int col = wc*32 + ct*8 + 2*lr;
                float2 w;
                w.x = acc[rt][ct][2*hh+0] + bias[col];
                w.y = acc[rt][ct][2*hh+1] + bias[col+1];
                *(float2*)(dst + ((size_t)(bb*NH + h)*Tn + tt)*HD + col) = w;
            }
}

// ============================================================
// Kernel 3: output projection, tf32 mma. Same tiling.
// ============================================================
__global__ __launch_bounds__(256) void out_mma(
    const float* __restrict__ Wout, const float* __restrict__ bout,
    float* __restrict__ out)
{
    __shared__ float s_a[128*20];
    __shared__ float s_b[16*68];

    const int tid = threadIdx.x, lane = tid & 31, warp = tid >> 5;
    const int wr = warp >> 1, wc = warp & 1;
    const int lq = lane >> 2, lr = lane & 3;
    const int row0 = blockIdx.y * 128, col0 = blockIdx.x * 64;

    const int ar = tid >> 2, ak = (tid & 3) << 2;
    const int bk = tid >> 4, bn = (tid & 15) << 2;

    float acc[2][4][4];
#pragma unroll
    for (int i = 0; i < 2; i++)
#pragma unroll
        for (int j = 0; j < 4; j++)
#pragma unroll
            for (int e = 0; e < 4; e++) acc[i][j][e] = 0.f;

    for (int k0 = 0; k0 < OUTD; k0 += 16) {
        float4 a0v = *(const float4*)(g_att + (size_t)(row0 + ar)      * OUTD + k0 + ak);
        float4 a1v = *(const float4*)(g_att + (size_t)(row0 + ar + 64) * OUTD + k0 + ak);
        float4 bv  = *(const float4*)(Wout + (size_t)(k0 + bk) * IND + col0 + bn);
        __syncthreads();
        s_a[ ar      *20 + ak+0] = tfs(a0v.x); s_a[ ar      *20 + ak+1] = tfs(a0v.y);
        s_a[ ar      *20 + ak+2] = tfs(a0v.z); s_a[ ar      *20 + ak+3] = tfs(a0v.w);
        s_a[(ar + 64)*20 + ak+0] = tfs(a1v.x); s_a[(ar + 64)*20 + ak+1] = tfs(a1v.y);
        s_a[(ar + 64)*20 + ak+2] = tfs(a1v.z); s_a[(ar + 64)*20 + ak+3] = tfs(a1v.w);
        s_b[bk*68 + bn+0] = tfs(bv.x); s_b[bk*68 + bn+1] = tfs(bv.y);
        s_b[bk*68 + bn+2] = tfs(bv.z); s_b[bk*68 + bn+3] = tfs(bv.w);
        __syncthreads();

#pragma unroll
        for (int ks = 0; ks < 2; ks++) {
            unsigned a[2][4], b[4][2];
#pragma unroll
            for (int rt = 0; rt < 2; rt++) {
                int r = wr*32 + rt*16 + lq, k = ks*8 + lr;
                a[rt][0] = __float_as_uint(s_a[ r   *20 + k]);
                a[rt][1] = __float_as_uint(s_a[(r+8)*20 + k]);
                a[rt][2] = __float_as_uint(s_a[ r   *20 + k+4]);
                a[rt][3] = __float_as_uint(s_a[(r+8)*20 + k+4]);
            }
#pragma unroll
            for (int ct = 0; ct < 4; ct++) {
                int n = wc*32 + ct*8 + lq, k = ks*8 + lr;
                b[ct][0] = __float_as_uint(s_b[ k   *68 + n]);
                b[ct][1] = __float_as_uint(s_b[(k+4)*68 + n]);
            }
#pragma unroll
            for (int rt = 0; rt < 2; rt++)
#pragma unroll
                for (int ct = 0; ct < 4; ct++)
                    mma8(acc[rt][ct], a[rt][0],a[rt][1],a[rt][2],a[rt][3], b[ct][0],b[ct][1]);
        }
    }

#pragma unroll
    for (int rt = 0; rt < 2; rt++)
#pragma unroll
        for (int ct = 0; ct < 4; ct++)
#pragma unroll
            for (int hh = 0; hh < 2; hh++) {
                int r   = row0 + wr*32 + rt*16 + lq + 8*hh;
                int col = wc*32 + ct*8 + 2*lr;
                float2 w;
                w.x = acc[rt][ct][2*hh+0] + bout[col0 + col];
                w.y = acc[rt][ct][2*hh+1] + bout[col0 + col+1];
                *(float2*)(out + (size_t)r * IND + col0 + col) = w;
            }
}

// ============================================================
// Kernel 2: attention, tf32 mma with relative position bias.
// Block: 64 q-rows x one (b,h), 4 warps (16 rows each).
// ============================================================
#define LDT 72
#define LDP 68
#define LPS 81
#define ATTN_SMEM ((2*64*LDT + 128*LDT + 4*16*LDP + 4*16*LPS) * (int)sizeof(float))  // 111,872 B

__global__ __launch_bounds__(128) void attn_mma(const float* __restrict__ rel_emb)
{
    extern __shared__ float sm[];
    float* s_k   = sm;                        // [64][LDT]  (also Q staging)
    float* s_vt  = sm + 64*LDT;               // [64][LDT]  V transposed
    float* s_rel = sm + 2*64*LDT;             // [128][LDT]
    float* s_p   = sm + 2*64*LDT + 128*LDT;   // per-warp [16][LDP]
    float* s_pos = s_p + 4*16*LDP;            // per-warp [16][LPS]

    const int tid = threadIdx.x, lane = tid & 31, warp = tid >> 5;
    const int lq = lane >> 2, lr = lane & 3;
    const int n0 = blockIdx.x * 64;
    const int bh = blockIdx.y;
    const size_t base = (size_t)bh * Tn * HD;
    float* wp  = s_p  + warp*16*LDP;
    float* wps = s_pos + warp*16*LPS;

    // ---- stage Q, load A-fragments into registers ----
    for (int e = tid; e < 64*16; e += 128) {
        int i = e >> 4, d4 = (e & 15) << 2;
        float4 v = *(const float4*)(g_q + base + (size_t)(n0 + i)*HD + d4);
        s_k[i*LDT + d4+0] = tfs(v.x); s_k[i*LDT + d4+1] = tfs(v.y);
        s_k[i*LDT + d4+2] = tfs(v.z); s_k[i*LDT + d4+3] = tfs(v.w);
    }
    __syncthreads();
    unsigned qa[8][4];
#pragma unroll
    for (int ks = 0; ks < 8; ks++) {
        int r = warp*16 + lq, k = ks*8 + lr;
        qa[ks][0] = __float_as_uint(s_k[ r   *LDT + k]);
        qa[ks][1] = __float_as_uint(s_k[(r+8)*LDT + k]);
        qa[ks][2] = __float_as_uint(s_k[ r   *LDT + k+4]);
        qa[ks][3] = __float_as_uint(s_k[(r+8)*LDT + k+4]);
    }
    __syncthreads();

    float o[8][4];
#pragma unroll
    for (int i = 0; i < 8; i++)
#pragma unroll
        for (int j = 0; j < 4; j++) o[i][j] = 0.f;
    float mi0 = -1e30f, mi1 = -1e30f, li0 = 0.f, li1 = 0.f;

    for (int m0 = 0; m0 < Tn; m0 += 64) {
        // ---- load K (tf32), V^T (tf32), Rel (tf32, clipped) ----
        for (int e = tid; e < 64*16; e += 128) {
            int i = e >> 4, d4 = (e & 15) << 2;
            float4 kv = *(const float4*)(g_k + base + (size_t)(m0 + i)*HD + d4);
            float4 vv = *(const float4*)(g_v + base + (size_t)(m0 + i)*HD + d4);
            s_k[i*LDT + d4+0] = tfs(kv.x); s_k[i*LDT + d4+1] = tfs(kv.y);
            s_k[i*LDT + d4+2] = tfs(kv.z); s_k[i*LDT + d4+3] = tfs(kv.w);
            s_vt[(d4+0)*LDT + i] = tfs(vv.x); s_vt[(d4+1)*LDT + i] = tfs(vv.y);
            s_vt[(d4+2)*LDT + i] = tfs(vv.z); s_vt[(d4+3)*LDT + i] = tfs(vv.w);
        }
        const int delta0 = n0 - m0;
        for (int e = tid; e < 128*16; e += 128) {
            int r = e >> 4, d4 = (e & 15) << 2;
            int dd = delta0 + r - 63;
            dd = dd < -MAXPOS ? -MAXPOS : (dd > MAXPOS ? MAXPOS : dd);
            float4 rv = *(const float4*)(rel_emb + (size_t)(dd + MAXPOS)*HD + d4);
            s_rel[r*LDT + d4+0] = tfs(rv.x); s_rel[r*LDT + d4+1] = tfs(rv.y);
            s_rel[r*LDT + d4+2] = tfs(rv.z); s_rel[r*LDT + d4+3] = tfs(rv.w);
        }
        __syncthreads();

        // ---- S = Q K^T ----
        float sc[8][4];
#pragma unroll
        for (int i = 0; i < 8; i++)
#pragma unroll
            for (int j = 0; j < 4; j++) sc[i][j] = 0.f;
#pragma unroll
        for (int ks = 0; ks < 8; ks++)
#pragma unroll
            for (int ct = 0; ct < 8; ct++) {
                int n = ct*8 + lq, k = ks*8 + lr;
                unsigned b0 = __float_as_uint(s_k[n*LDT + k]);
                unsigned b1 = __float_as_uint(s_k[n*LDT + k+4]);
                mma8(sc[ct], qa[ks][0],qa[ks][1],qa[ks][2],qa[ks][3], b0, b1);
            }

        // ---- Pos = Q Rel^T (80 cols needed by this warp) ----
        float pp[10][4];
#pragma unroll
        for (int i = 0; i < 10; i++)
#pragma unroll
            for (int j = 0; j < 4; j++) pp[i][j] = 0.f;
#pragma unroll
        for (int ks = 0; ks < 8; ks++)
#pragma unroll
            for (int ct = 0; ct < 10; ct++) {
                int n = warp*16 + ct*8 + lq, k = ks*8 + lr;
                unsigned b0 = __float_as_uint(s_rel[n*LDT + k]);
                unsigned b1 = __float_as_uint(s_rel[n*LDT + k+4]);
                mma8(pp[ct], qa[ks][0],qa[ks][1],qa[ks][2],qa[ks][3], b0, b1);
            }
#pragma unroll
        for (int ct = 0; ct < 10; ct++) {
            int c = ct*8 + 2*lr;
            wps[ lq   *LPS + c  ] = pp[ct][0];
            wps[ lq   *LPS + c+1] = pp[ct][1];
            wps[(lq+8)*LPS + c  ] = pp[ct][2];
            wps[(lq+8)*LPS + c+1] = pp[ct][3];
        }
        __syncwarp();

        // ---- add pos (gather on diagonal index), scale, online softmax ----
        float rmax0 = -1e30f, rmax1 = -1e30f;
#pragma unroll
        for (int ct = 0; ct < 8; ct++)
#pragma unroll
            for (int c = 0; c < 2; c++) {
                int m  = ct*8 + 2*lr + c;
                int u0 = lq - m + 63;
                float v0 = (sc[ct][c]   + wps[ lq   *LPS + u0    ]) * 0.125f;
                float v1 = (sc[ct][2+c] + wps[(lq+8)*LPS + u0 + 8]) * 0.125f;
                sc[ct][c] = v0; sc[ct][2+c] = v1;
                rmax0 = fmaxf(rmax0, v0); rmax1 = fmaxf(rmax1, v1);
            }
        rmax0 = fmaxf(rmax0, __shfl_xor_sync(~0u, rmax0, 1));
        rmax0 = fmaxf(rmax0, __shfl_xor_sync(~0u, rmax0, 2));
        rmax1 = fmaxf(rmax1, __shfl_xor_sync(~0u, rmax1, 1));
        rmax1 = fmaxf(rmax1, __shfl_xor_sync(~0u, rmax1, 2));

        float nm0 = fmaxf(mi0, rmax0), nm1 = fmaxf(mi1, rmax1);
        float cor0 = __expf(mi0 - nm0), cor1 = __expf(mi1 - nm1);
        mi0 = nm0; mi1 = nm1;

        float rs0 = 0.f, rs1 = 0.f;
#pragma unroll
        for (int ct = 0; ct < 8; ct++)
#pragma unroll
            for (int c = 0; c < 2; c++) {
                int m = ct*8 + 2*lr + c;
                float p0 = __expf(sc[ct][c]   - nm0); rs0 += p0;
                float p1 = __expf(sc[ct][2+c] - nm1); rs1 += p1;
                wp[ lq   *LDP + m] = tfs(p0);
                wp[(lq+8)*LDP + m] = tfs(p1);
            }
        rs0 += __shfl_xor_sync(~0u, rs0, 1); rs0 += __shfl_xor_sync(~0u, rs0, 2);
        rs1 += __shfl_xor_sync(~0u, rs1, 1); rs1 += __shfl_xor_sync(~0u, rs1, 2);
        li0 = li0*cor0 + rs0; li1 = li1*cor1 + rs1;
#pragma unroll
        for (int ct = 0; ct < 8; ct++) {
            o[ct][0] *= cor0; o[ct][1] *= cor0;
            o[ct][2] *= cor1; o[ct][3] *= cor1;
        }
        __syncwarp();

        // ---- O += P V ----
#pragma unroll
        for (int ks = 0; ks < 8; ks++) {
            int k = ks*8 + lr;
            unsigned a0 = __float_as_uint(wp[ lq   *LDP + k]);
            unsigned a1 = __float_as_uint(wp[(lq+8)*LDP + k]);
            unsigned a2 = __float_as_uint(wp[ lq   *LDP + k+4]);
            unsigned a3 = __float_as_uint(wp[(lq+8)*LDP + k+4]);
#pragma unroll
            for (int ct = 0; ct < 8; ct++) {
                int d = ct*8 + lq;
                unsigned b0 = __float_as_uint(s_vt[d*LDT + k]);
                unsigned b1 = __float_as_uint(s_vt[d*LDT + k+4]);
                mma8(o[ct], a0, a1, a2, a3, b0, b1);
            }
        }
        __syncthreads();
    }

    // ---- normalize, write [b, t, h*64+d] ----
    const float inv0 = 1.f / li0, inv1 = 1.f / li1;
    const int b_ = bh >> 3, h_ = bh & 7;
#pragma unroll
    for (int ct = 0; ct < 8; ct++) {
        int col = h_*HD + ct*8 + 2*lr;
        int r0  = n0 + warp*16 + lq;
        float2 w0; w0.x = o[ct][0]*inv0; w0.y = o[ct][1]*inv0;
        *(float2*)(g_att + ((size_t)(b_*Tn + r0    )*OUTD + col)) = w0;
        float2 w1; w1.x = o[ct][2]*inv1; w1.y = o[ct][3]*inv1;
        *(float2*)(g_att + ((size_t)(b_*Tn + r0 + 8)*OUTD + col)) = w1;
    }
}

// ============================================================
extern "C" void kernel_launch(void* const* d_in, const int* in_sizes, int n_in,
                              void* d_out, int out_size)
{
    const float* x    = (const float*)d_in[0];
    const float* Wq   = (const float*)d_in[1];
    const float* bq   = (const float*)d_in[2];
    const float* Wkv  = (const float*)d_in[3];
    const float* bkv  = (const float*)d_in[4];
    const float* Wout = (const float*)d_in[5];
    const float* bout = (const float*)d_in[6];
    const float* rel  = (const float*)d_in[7];
    float* out = (float*)d_out;

    cudaFuncSetAttribute(attn_mma,
                         cudaFuncAttributeMaxDynamicSharedMemorySize, ATTN_SMEM);

    qkv_mma<<<dim3(24, 64), 256>>>(x, Wq, bq, Wkv, bkv);
    attn_mma<<<dim3(16, 64), 128, ATTN_SMEM>>>(rel);
    out_mma<<<dim3(8, 64), 256>>>(Wout, bout, out);
}